// round 1
// baseline (speedup 1.0000x reference)
#include <cuda_runtime.h>

// Batched Kabsch RMSD.
// inputs (metadata order): input [8192, 1536] f32, target [8192, 1536] f32,
//                          num_atoms [8192] int64-or-int32 (runtime-detected)
// output: [8192] f32 rmsd.

constexpr int NATOMS  = 512;
constexpr int ROWF    = NATOMS * 3;   // 1536 floats per row
constexpr int THREADS = 256;
constexpr int NWARPS  = THREADS / 32;

__global__ __launch_bounds__(THREADS) void kabsch_rmsd_kernel(
    const float* __restrict__ inp,
    const float* __restrict__ tgt,
    const int*   __restrict__ na32,   // raw words of num_atoms buffer
    float*       __restrict__ out)
{
    __shared__ float s_src[ROWF];
    __shared__ float s_dst[ROWF];
    __shared__ float s_red[NWARPS][17];

    const int b = blockIdx.x;
    const int t = threadIdx.x;

    // ---- coalesced float4 staging of both rows into SMEM ----
    const float4* src4 = reinterpret_cast<const float4*>(inp) + (size_t)b * (ROWF / 4);
    const float4* dst4 = reinterpret_cast<const float4*>(tgt) + (size_t)b * (ROWF / 4);
    float4* ss = reinterpret_cast<float4*>(s_src);
    float4* sd = reinterpret_cast<float4*>(s_dst);
    ss[t] = src4[t];
    sd[t] = dst4[t];
    if (t < (ROWF / 4 - THREADS)) {            // 384 - 256 = 128 extra f4
        ss[THREADS + t] = src4[THREADS + t];
        sd[THREADS + t] = dst4[THREADS + t];
    }

    // ---- num_atoms dtype detection: values are always >= 16, so if the
    //      second 32-bit word is 0 the buffer must be little-endian int64
    //      (word 1 = high half of element 0). Reads stay in-bounds under
    //      both interpretations. ----
    int n;
    {
        const int probe = __ldg(&na32[1]);
        n = (probe == 0) ? __ldg(&na32[2 * b]) : __ldg(&na32[b]);
    }
    __syncthreads();

    // ---- per-thread raw-moment accumulation (2 atoms per thread) ----
    // acc[0..2]  = sum src (x,y,z)
    // acc[3..5]  = sum dst (x,y,z)
    // acc[6..14] = sum src_i * dst_j (row-major 3x3)
    // acc[15]    = sum |src|^2 ; acc[16] = sum |dst|^2
    float acc[17];
#pragma unroll
    for (int i = 0; i < 17; ++i) acc[i] = 0.0f;

#pragma unroll
    for (int k = 0; k < 2; ++k) {
        const int a = t + k * THREADS;
        if (a < n) {
            const float sx = s_src[3 * a + 0];
            const float sy = s_src[3 * a + 1];
            const float sz = s_src[3 * a + 2];
            const float dx = s_dst[3 * a + 0];
            const float dy = s_dst[3 * a + 1];
            const float dz = s_dst[3 * a + 2];
            acc[0] += sx;  acc[1] += sy;  acc[2] += sz;
            acc[3] += dx;  acc[4] += dy;  acc[5] += dz;
            acc[6]  += sx * dx;  acc[7]  += sx * dy;  acc[8]  += sx * dz;
            acc[9]  += sy * dx;  acc[10] += sy * dy;  acc[11] += sy * dz;
            acc[12] += sz * dx;  acc[13] += sz * dy;  acc[14] += sz * dz;
            acc[15] += sx * sx + sy * sy + sz * sz;
            acc[16] += dx * dx + dy * dy + dz * dz;
        }
    }

    // ---- warp reduction ----
#pragma unroll
    for (int o = 16; o > 0; o >>= 1) {
#pragma unroll
        for (int i = 0; i < 17; ++i)
            acc[i] += __shfl_xor_sync(0xffffffffu, acc[i], o);
    }
    const int wid = t >> 5;
    const int lid = t & 31;
    if (lid == 0) {
#pragma unroll
        for (int i = 0; i < 17; ++i) s_red[wid][i] = acc[i];
    }
    __syncthreads();

    // ---- final scalar stage: one thread, double precision ----
    if (t == 0) {
        double v[17];
#pragma unroll
        for (int i = 0; i < 17; ++i) {
            double s = 0.0;
#pragma unroll
            for (int w = 0; w < NWARPS; ++w) s += (double)s_red[w][i];
            v[i] = s;
        }

        const double nn = (double)n;

        // centered correlation matrix R = M - (sum_s)(sum_d)^T / n
        double R[3][3];
#pragma unroll
        for (int i = 0; i < 3; ++i)
#pragma unroll
            for (int j = 0; j < 3; ++j)
                R[i][j] = v[6 + 3 * i + j] - v[i] * v[3 + j] / nn;

        const double sq = v[15] + v[16]
            - (v[0] * v[0] + v[1] * v[1] + v[2] * v[2]) / nn
            - (v[3] * v[3] + v[4] * v[4] + v[5] * v[5]) / nn;

        const double detR =
              R[0][0] * (R[1][1] * R[2][2] - R[1][2] * R[2][1])
            - R[0][1] * (R[1][0] * R[2][2] - R[1][2] * R[2][0])
            + R[0][2] * (R[1][0] * R[2][1] - R[1][1] * R[2][0]);

        // A = R^T R (symmetric PSD); singular values of R = sqrt(eig(A))
        double A00 = R[0][0]*R[0][0] + R[1][0]*R[1][0] + R[2][0]*R[2][0];
        double A11 = R[0][1]*R[0][1] + R[1][1]*R[1][1] + R[2][1]*R[2][1];
        double A22 = R[0][2]*R[0][2] + R[1][2]*R[1][2] + R[2][2]*R[2][2];
        double A01 = R[0][0]*R[0][1] + R[1][0]*R[1][1] + R[2][0]*R[2][1];
        double A02 = R[0][0]*R[0][2] + R[1][0]*R[1][2] + R[2][0]*R[2][2];
        double A12 = R[0][1]*R[0][2] + R[1][1]*R[1][2] + R[2][1]*R[2][2];

        const double q  = (A00 + A11 + A22) / 3.0;
        const double p1 = A01 * A01 + A02 * A02 + A12 * A12;
        const double b0 = A00 - q, b1 = A11 - q, b2 = A22 - q;
        const double p2 = b0 * b0 + b1 * b1 + b2 * b2 + 2.0 * p1;

        double e1, e2, e3;
        if (p2 <= 1e-30) {
            e1 = e2 = e3 = q;
        } else {
            const double p    = sqrt(p2 / 6.0);
            const double ip   = 1.0 / p;
            const double B00 = b0 * ip, B11 = b1 * ip, B22 = b2 * ip;
            const double B01 = A01 * ip, B02 = A02 * ip, B12 = A12 * ip;
            double detB =
                  B00 * (B11 * B22 - B12 * B12)
                - B01 * (B01 * B22 - B12 * B02)
                + B02 * (B01 * B12 - B11 * B02);
            double r = detB * 0.5;
            r = fmin(1.0, fmax(-1.0, r));
            const double phi = acos(r) / 3.0;
            e1 = q + 2.0 * p * cos(phi);
            e3 = q + 2.0 * p * cos(phi + 2.0943951023931957); // + 2*pi/3
            e2 = 3.0 * q - e1 - e3;
        }

        const double s1 = sqrt(fmax(e1, 0.0));   // largest
        const double s2 = sqrt(fmax(e2, 0.0));
        const double s3 = sqrt(fmax(e3, 0.0));   // smallest

        const double d  = (detR >= 0.0) ? 1.0 : -1.0;
        const double trace_opt = s1 + s2 + d * s3;

        const double msd = (sq - 2.0 * trace_opt) / nn;
        out[b] = (float)sqrt(fmax(msd, 0.0));
    }
}

extern "C" void kernel_launch(void* const* d_in, const int* in_sizes, int n_in,
                              void* d_out, int out_size)
{
    const float* inp  = (const float*)d_in[0];
    const float* tgt  = (const float*)d_in[1];
    const int*   na32 = (const int*)d_in[2];   // dtype detected in-kernel
    float*       out  = (float*)d_out;

    const int batch = out_size;                // 8192 rows
    kabsch_rmsd_kernel<<<batch, THREADS>>>(inp, tgt, na32, out);
}

// round 3
// speedup vs baseline: 6.4834x; 6.4834x over previous
#include <cuda_runtime.h>

// Batched Kabsch RMSD — two-kernel version.
// K1: per-row moment reduction (memory-bound), writes 17 moments/row to scratch.
// K2: one thread per row, 3x3 eigen epilogue (parallel, no serial fp64 chain).

constexpr int NATOMS  = 512;
constexpr int ROWF    = NATOMS * 3;   // 1536 floats per row
constexpr int THREADS = 256;
constexpr int NWARPS  = THREADS / 32;
constexpr int BATCH   = 8192;

// scratch laid out [17][BATCH] so the epilogue kernel reads coalesced
__device__ float g_moments[17 * BATCH];

__global__ __launch_bounds__(THREADS) void kabsch_reduce(
    const float* __restrict__ inp,
    const float* __restrict__ tgt,
    const int*   __restrict__ na32)
{
    __shared__ float s_src[ROWF];
    __shared__ float s_dst[ROWF];
    __shared__ float s_red[NWARPS][17];

    const int b = blockIdx.x;
    const int t = threadIdx.x;

    // coalesced float4 staging of both rows into SMEM
    const float4* src4 = reinterpret_cast<const float4*>(inp) + (size_t)b * (ROWF / 4);
    const float4* dst4 = reinterpret_cast<const float4*>(tgt) + (size_t)b * (ROWF / 4);
    float4* ss = reinterpret_cast<float4*>(s_src);
    float4* sd = reinterpret_cast<float4*>(s_dst);
    ss[t] = src4[t];
    sd[t] = dst4[t];
    if (t < (ROWF / 4 - THREADS)) {            // 384 - 256 = 128 extra f4
        ss[THREADS + t] = src4[THREADS + t];
        sd[THREADS + t] = dst4[THREADS + t];
    }

    // num_atoms dtype probe: values always >= 16, so word1==0 <=> int64 layout
    int n;
    {
        const int probe = __ldg(&na32[1]);
        n = (probe == 0) ? __ldg(&na32[2 * b]) : __ldg(&na32[b]);
    }
    __syncthreads();

    // per-thread raw-moment accumulation (2 atoms per thread)
    // acc[0..2]=sum s ; acc[3..5]=sum d ; acc[6..14]=sum s_i d_j ;
    // acc[15]=sum|s|^2 ; acc[16]=sum|d|^2
    float acc[17];
#pragma unroll
    for (int i = 0; i < 17; ++i) acc[i] = 0.0f;

#pragma unroll
    for (int k = 0; k < 2; ++k) {
        const int a = t + k * THREADS;
        if (a < n) {
            const float sx = s_src[3 * a + 0];
            const float sy = s_src[3 * a + 1];
            const float sz = s_src[3 * a + 2];
            const float dx = s_dst[3 * a + 0];
            const float dy = s_dst[3 * a + 1];
            const float dz = s_dst[3 * a + 2];
            acc[0] += sx;  acc[1] += sy;  acc[2] += sz;
            acc[3] += dx;  acc[4] += dy;  acc[5] += dz;
            acc[6]  += sx * dx;  acc[7]  += sx * dy;  acc[8]  += sx * dz;
            acc[9]  += sy * dx;  acc[10] += sy * dy;  acc[11] += sy * dz;
            acc[12] += sz * dx;  acc[13] += sz * dy;  acc[14] += sz * dz;
            acc[15] += sx * sx + sy * sy + sz * sz;
            acc[16] += dx * dx + dy * dy + dz * dz;
        }
    }

    // warp tree reduction (17 values)
#pragma unroll
    for (int o = 16; o > 0; o >>= 1) {
#pragma unroll
        for (int i = 0; i < 17; ++i)
            acc[i] += __shfl_xor_sync(0xffffffffu, acc[i], o);
    }
    const int wid = t >> 5;
    const int lid = t & 31;
    if (lid == 0) {
#pragma unroll
        for (int i = 0; i < 17; ++i) s_red[wid][i] = acc[i];
    }
    __syncthreads();

    // parallel cross-warp combine: 17 threads, one moment each
    if (t < 17) {
        float s = 0.0f;
#pragma unroll
        for (int w = 0; w < NWARPS; ++w) s += s_red[w][t];
        g_moments[t * BATCH + b] = s;
    }
}

__global__ __launch_bounds__(256) void kabsch_epilogue(
    const int* __restrict__ na32,
    float*     __restrict__ out)
{
    const int b = blockIdx.x * blockDim.x + threadIdx.x;
    if (b >= BATCH) return;

    int n;
    {
        const int probe = __ldg(&na32[1]);
        n = (probe == 0) ? __ldg(&na32[2 * b]) : __ldg(&na32[b]);
    }

    double v[17];
#pragma unroll
    for (int i = 0; i < 17; ++i) v[i] = (double)g_moments[i * BATCH + b];

    const double nn  = (double)n;
    const double inv = 1.0 / nn;

    // centered correlation matrix R = M - (sum_s)(sum_d)^T / n
    double R[3][3];
#pragma unroll
    for (int i = 0; i < 3; ++i)
#pragma unroll
        for (int j = 0; j < 3; ++j)
            R[i][j] = v[6 + 3 * i + j] - v[i] * v[3 + j] * inv;

    const double sq = v[15] + v[16]
        - (v[0] * v[0] + v[1] * v[1] + v[2] * v[2]) * inv
        - (v[3] * v[3] + v[4] * v[4] + v[5] * v[5]) * inv;

    const double detR =
          R[0][0] * (R[1][1] * R[2][2] - R[1][2] * R[2][1])
        - R[0][1] * (R[1][0] * R[2][2] - R[1][2] * R[2][0])
        + R[0][2] * (R[1][0] * R[2][1] - R[1][1] * R[2][0]);

    // A = R^T R (symmetric PSD); singular values of R = sqrt(eig(A))
    const double A00 = R[0][0]*R[0][0] + R[1][0]*R[1][0] + R[2][0]*R[2][0];
    const double A11 = R[0][1]*R[0][1] + R[1][1]*R[1][1] + R[2][1]*R[2][1];
    const double A22 = R[0][2]*R[0][2] + R[1][2]*R[1][2] + R[2][2]*R[2][2];
    const double A01 = R[0][0]*R[0][1] + R[1][0]*R[1][1] + R[2][0]*R[2][1];
    const double A02 = R[0][0]*R[0][2] + R[1][0]*R[1][2] + R[2][0]*R[2][2];
    const double A12 = R[0][1]*R[0][2] + R[1][1]*R[1][2] + R[2][1]*R[2][2];

    const double q  = (A00 + A11 + A22) * (1.0 / 3.0);
    const double p1 = A01 * A01 + A02 * A02 + A12 * A12;
    const double b0 = A00 - q, b1 = A11 - q, b2 = A22 - q;
    const double p2 = b0 * b0 + b1 * b1 + b2 * b2 + 2.0 * p1;

    double e1, e2, e3;
    if (p2 <= 1e-30) {
        e1 = e2 = e3 = q;
    } else {
        const double p   = sqrt(p2 / 6.0);
        const double ip  = 1.0 / p;
        const double B00 = b0 * ip, B11 = b1 * ip, B22 = b2 * ip;
        const double B01 = A01 * ip, B02 = A02 * ip, B12 = A12 * ip;
        double r =
            ( B00 * (B11 * B22 - B12 * B12)
            - B01 * (B01 * B22 - B12 * B02)
            + B02 * (B01 * B12 - B11 * B02) ) * 0.5;
        r = fmin(1.0, fmax(-1.0, r));
        // fast float trig (MUFU-backed): abs error ~1e-7 in phi, far inside
        // the 1e-3 rel-err budget.
        const float phi = acosf((float)r) * (1.0f / 3.0f);
        const double c1 = (double)__cosf(phi);
        const double c3 = (double)__cosf(phi + 2.0943951f); // + 2*pi/3
        e1 = q + 2.0 * p * c1;
        e3 = q + 2.0 * p * c3;
        e2 = 3.0 * q - e1 - e3;
    }

    const double s1 = sqrt(fmax(e1, 0.0));   // largest
    const double s2 = sqrt(fmax(e2, 0.0));
    const double s3 = sqrt(fmax(e3, 0.0));   // smallest

    const double d  = (detR >= 0.0) ? 1.0 : -1.0;
    const double trace_opt = s1 + s2 + d * s3;

    const double msd = (sq - 2.0 * trace_opt) * inv;
    out[b] = (float)sqrt(fmax(msd, 0.0));
}

extern "C" void kernel_launch(void* const* d_in, const int* in_sizes, int n_in,
                              void* d_out, int out_size)
{
    const float* inp  = (const float*)d_in[0];
    const float* tgt  = (const float*)d_in[1];
    const int*   na32 = (const int*)d_in[2];
    float*       out  = (float*)d_out;

    kabsch_reduce<<<BATCH, THREADS>>>(inp, tgt, na32);
    kabsch_epilogue<<<(BATCH + 255) / 256, 256>>>(na32, out);
}

// round 4
// speedup vs baseline: 13.4298x; 2.0714x over previous
#include <cuda_runtime.h>

// Batched Kabsch RMSD — two kernels, fp32 throughout (sm_103a fp64 is ~18cyc/op).
// K1: register-direct moment reduction, 128 threads/row (4 atoms/thread).
// K2: one thread per row, fp32 3x3 eigen epilogue.

constexpr int BATCH   = 8192;
constexpr int ROWF4   = 384;          // 1536 floats = 384 float4 per row
constexpr int TPB     = 128;          // threads per row-block
constexpr int NW      = TPB / 32;

// scratch [17][BATCH]: coalesced writes from K1, coalesced reads in K2
__device__ float g_moments[17 * BATCH];

__device__ __forceinline__ void accum_atom(float* acc,
                                           float sx, float sy, float sz,
                                           float dx, float dy, float dz)
{
    acc[0] += sx;  acc[1] += sy;  acc[2] += sz;
    acc[3] += dx;  acc[4] += dy;  acc[5] += dz;
    acc[6]  = fmaf(sx, dx, acc[6]);   acc[7]  = fmaf(sx, dy, acc[7]);   acc[8]  = fmaf(sx, dz, acc[8]);
    acc[9]  = fmaf(sy, dx, acc[9]);   acc[10] = fmaf(sy, dy, acc[10]);  acc[11] = fmaf(sy, dz, acc[11]);
    acc[12] = fmaf(sz, dx, acc[12]);  acc[13] = fmaf(sz, dy, acc[13]);  acc[14] = fmaf(sz, dz, acc[14]);
    acc[15] = fmaf(sx, sx, fmaf(sy, sy, fmaf(sz, sz, acc[15])));
    acc[16] = fmaf(dx, dx, fmaf(dy, dy, fmaf(dz, dz, acc[16])));
}

__global__ __launch_bounds__(TPB) void kabsch_reduce(
    const float* __restrict__ inp,
    const float* __restrict__ tgt,
    const int*   __restrict__ na32)
{
    __shared__ float s_red[NW][17];

    const int b = blockIdx.x;
    const int t = threadIdx.x;

    // thread t owns atoms 4t..4t+3 == float4 indices 3t..3t+2 (12 contiguous floats)
    const float4* src4 = reinterpret_cast<const float4*>(inp) + (size_t)b * ROWF4 + 3 * t;
    const float4* dst4 = reinterpret_cast<const float4*>(tgt) + (size_t)b * ROWF4 + 3 * t;
    const float4 s0 = src4[0], s1 = src4[1], s2 = src4[2];
    const float4 d0 = dst4[0], d1 = dst4[1], d2 = dst4[2];

    // num_atoms dtype probe: values always >= 16, so word1==0 <=> int64 layout
    int n;
    {
        const int probe = __ldg(&na32[1]);
        n = (probe == 0) ? __ldg(&na32[2 * b]) : __ldg(&na32[b]);
    }

    float acc[17];
#pragma unroll
    for (int i = 0; i < 17; ++i) acc[i] = 0.0f;

    const int a0 = 4 * t;
    if (a0 + 0 < n) accum_atom(acc, s0.x, s0.y, s0.z, d0.x, d0.y, d0.z);
    if (a0 + 1 < n) accum_atom(acc, s0.w, s1.x, s1.y, d0.w, d1.x, d1.y);
    if (a0 + 2 < n) accum_atom(acc, s1.z, s1.w, s2.x, d1.z, d1.w, d2.x);
    if (a0 + 3 < n) accum_atom(acc, s2.y, s2.z, s2.w, d2.y, d2.z, d2.w);

    // warp butterfly reduction (17 values)
#pragma unroll
    for (int o = 16; o > 0; o >>= 1) {
#pragma unroll
        for (int i = 0; i < 17; ++i)
            acc[i] += __shfl_xor_sync(0xffffffffu, acc[i], o);
    }
    const int wid = t >> 5;
    if ((t & 31) == 0) {
#pragma unroll
        for (int i = 0; i < 17; ++i) s_red[wid][i] = acc[i];
    }
    __syncthreads();

    if (t < 17) {
        float s = s_red[0][t] + s_red[1][t] + s_red[2][t] + s_red[3][t];
        g_moments[t * BATCH + b] = s;
    }
}

__global__ __launch_bounds__(64) void kabsch_epilogue(
    const int* __restrict__ na32,
    float*     __restrict__ out)
{
    const int b = blockIdx.x * blockDim.x + threadIdx.x;
    if (b >= BATCH) return;

    int n;
    {
        const int probe = __ldg(&na32[1]);
        n = (probe == 0) ? __ldg(&na32[2 * b]) : __ldg(&na32[b]);
    }

    float v[17];
#pragma unroll
    for (int i = 0; i < 17; ++i) v[i] = g_moments[i * BATCH + b];

    const float inv = 1.0f / (float)n;

    // centered correlation matrix R = M - (sum_s)(sum_d)^T / n
    float R[3][3];
#pragma unroll
    for (int i = 0; i < 3; ++i)
#pragma unroll
        for (int j = 0; j < 3; ++j)
            R[i][j] = v[6 + 3 * i + j] - v[i] * v[3 + j] * inv;

    const float sq = v[15] + v[16]
        - (v[0] * v[0] + v[1] * v[1] + v[2] * v[2]) * inv
        - (v[3] * v[3] + v[4] * v[4] + v[5] * v[5]) * inv;

    const float detR =
          R[0][0] * (R[1][1] * R[2][2] - R[1][2] * R[2][1])
        - R[0][1] * (R[1][0] * R[2][2] - R[1][2] * R[2][0])
        + R[0][2] * (R[1][0] * R[2][1] - R[1][1] * R[2][0]);

    // A = R^T R (symmetric PSD); singular values of R = sqrt(eig(A))
    const float A00 = R[0][0]*R[0][0] + R[1][0]*R[1][0] + R[2][0]*R[2][0];
    const float A11 = R[0][1]*R[0][1] + R[1][1]*R[1][1] + R[2][1]*R[2][1];
    const float A22 = R[0][2]*R[0][2] + R[1][2]*R[1][2] + R[2][2]*R[2][2];
    const float A01 = R[0][0]*R[0][1] + R[1][0]*R[1][1] + R[2][0]*R[2][1];
    const float A02 = R[0][0]*R[0][2] + R[1][0]*R[1][2] + R[2][0]*R[2][2];
    const float A12 = R[0][1]*R[0][2] + R[1][1]*R[1][2] + R[2][1]*R[2][2];

    const float q  = (A00 + A11 + A22) * (1.0f / 3.0f);
    const float p1 = A01 * A01 + A02 * A02 + A12 * A12;
    const float b0 = A00 - q, b1 = A11 - q, b2 = A22 - q;
    const float p2 = b0 * b0 + b1 * b1 + b2 * b2 + 2.0f * p1;

    float e1, e2, e3;
    if (p2 <= 1e-12f) {
        e1 = e2 = e3 = q;
    } else {
        const float p   = sqrtf(p2 * (1.0f / 6.0f));
        const float ip  = 1.0f / p;
        const float B00 = b0 * ip, B11 = b1 * ip, B22 = b2 * ip;
        const float B01 = A01 * ip, B02 = A02 * ip, B12 = A12 * ip;
        float r =
            ( B00 * (B11 * B22 - B12 * B12)
            - B01 * (B01 * B22 - B12 * B02)
            + B02 * (B01 * B12 - B11 * B02) ) * 0.5f;
        r = fminf(1.0f, fmaxf(-1.0f, r));
        const float phi = acosf(r) * (1.0f / 3.0f);
        const float c1 = __cosf(phi);
        const float c3 = __cosf(phi + 2.0943951023931953f); // + 2*pi/3
        e1 = q + 2.0f * p * c1;
        e3 = q + 2.0f * p * c3;
        e2 = 3.0f * q - e1 - e3;
    }

    const float s1 = sqrtf(fmaxf(e1, 0.0f));   // largest
    const float s2 = sqrtf(fmaxf(e2, 0.0f));
    const float s3 = sqrtf(fmaxf(e3, 0.0f));   // smallest

    const float d  = (detR >= 0.0f) ? 1.0f : -1.0f;
    const float trace_opt = s1 + s2 + d * s3;

    const float msd = (sq - 2.0f * trace_opt) * inv;
    out[b] = sqrtf(fmaxf(msd, 0.0f));
}

extern "C" void kernel_launch(void* const* d_in, const int* in_sizes, int n_in,
                              void* d_out, int out_size)
{
    const float* inp  = (const float*)d_in[0];
    const float* tgt  = (const float*)d_in[1];
    const int*   na32 = (const int*)d_in[2];
    float*       out  = (float*)d_out;

    kabsch_reduce<<<BATCH, TPB>>>(inp, tgt, na32);
    kabsch_epilogue<<<BATCH / 64, 64>>>(na32, out);
}